// round 1
// baseline (speedup 1.0000x reference)
#include <cuda_runtime.h>
#include <cuda_bf16.h>
#include <math.h>

// Problem constants
#define BB 2
#define SS 2048
#define DD 1024
#define HH 16
#define DHH 64
#define MM 4096
#define ROWS (BB*SS)          // 4096
#define EPS 1e-6f

// ---------------- scratch (static device globals; no allocations) -----------
__device__ float g_h[ROWS*DD];        // ln1 out
__device__ float g_q[ROWS*DD];
__device__ float g_k[ROWS*DD];
__device__ float g_v[ROWS*DD];
__device__ float g_ctx[ROWS*DD];
__device__ float g_mlpin[ROWS*DD];    // attn_out + x
__device__ float g_h2[ROWS*DD];       // ln2 out
__device__ float g_mid[ROWS*MM];      // gelu(h2@w1+b1)

// ---------------- LayerNorm: one block per row, 256 threads -----------------
__global__ void ln_kernel(const float* __restrict__ x,
                          const float* __restrict__ gamma,
                          const float* __restrict__ beta,
                          float* __restrict__ out)
{
    __shared__ float red0[8], red1[8];
    int row = blockIdx.x;
    int t = threadIdx.x;
    const float* xr = x + (size_t)row * DD;
    float v[4];
    float sum = 0.f, sq = 0.f;
#pragma unroll
    for (int i = 0; i < 4; i++) {
        v[i] = xr[t + i*256];
        sum += v[i];
        sq  += v[i]*v[i];
    }
#pragma unroll
    for (int o = 16; o; o >>= 1) {
        sum += __shfl_xor_sync(0xffffffffu, sum, o);
        sq  += __shfl_xor_sync(0xffffffffu, sq,  o);
    }
    if ((t & 31) == 0) { red0[t >> 5] = sum; red1[t >> 5] = sq; }
    __syncthreads();
    if (t < 32) {
        float s = (t < 8) ? red0[t] : 0.f;
        float q = (t < 8) ? red1[t] : 0.f;
#pragma unroll
        for (int o = 4; o; o >>= 1) {
            s += __shfl_xor_sync(0xffffffffu, s, o);
            q += __shfl_xor_sync(0xffffffffu, q, o);
        }
        if (t == 0) { red0[0] = s; red1[0] = q; }
    }
    __syncthreads();
    float mean = red0[0] * (1.f/ (float)DD);
    float var  = red1[0] * (1.f/ (float)DD) - mean*mean;
    float rstd = rsqrtf(var + EPS);
    float* orow = out + (size_t)row * DD;
#pragma unroll
    for (int i = 0; i < 4; i++) {
        int c = t + i*256;
        orow[c] = (v[i] - mean) * rstd * gamma[c] + beta[c];
    }
}

// ---------------- RoPE: rotate consecutive pairs in q and k -----------------
__global__ void rope_kernel(float* __restrict__ q, float* __restrict__ k)
{
    int idx = blockIdx.x * 256 + threadIdx.x;   // pair index, total 2^21
    int i = idx & 31;
    int h = (idx >> 5) & 15;
    int s = (idx >> 9) & 2047;
    int b = idx >> 20;
    float freq = powf(10000.0f, -((float)(2*i)) / 64.0f);
    float ang = (float)s * freq;
    float sn, cs;
    sincosf(ang, &sn, &cs);
    size_t base = ((size_t)(b*SS + s)) * DD + h*DHH + 2*i;
    float a0 = q[base], b0 = q[base+1];
    q[base]   = a0*cs - b0*sn;
    q[base+1] = a0*sn + b0*cs;
    a0 = k[base]; b0 = k[base+1];
    k[base]   = a0*cs - b0*sn;
    k[base+1] = a0*sn + b0*cs;
}

// ---------------- SGEMM: C = A[MxK] @ B[KxN] (+bias)(+gelu)(+resid) ---------
// BM=BN=128, BK=8, 256 threads, 8x8 microtile (cols split 2x4 for conflict-free LDS.128)
__device__ __forceinline__ float gelu_f(float x) {
    float x3 = x*x*x;
    float t = tanhf(0.7978845608028654f * (x + 0.044715f * x3));
    return 0.5f * x * (1.f + t);
}

__global__ void sgemm(const float* __restrict__ A, const float* __restrict__ B,
                      float* __restrict__ C, int M, int N, int K,
                      const float* __restrict__ bias,
                      const float* __restrict__ resid,
                      int do_gelu)
{
    __shared__ float As[8][128];   // k-major (transposed)
    __shared__ float Bs[8][128];
    int bx = blockIdx.x, by = blockIdx.y;
    int tid = threadIdx.x;
    int tx = tid & 15, ty = tid >> 4;

    float acc[8][8];
#pragma unroll
    for (int i = 0; i < 8; i++)
#pragma unroll
        for (int j = 0; j < 8; j++) acc[i][j] = 0.f;

    const float* Ab = A + (size_t)by * 128 * K;
    const float* Bb = B + (size_t)bx * 128;

    int a_row  = tid >> 1;           // 0..127
    int a_col4 = (tid & 1) * 4;      // 0 or 4
    int b_row  = tid >> 5;           // 0..7
    int b_col4 = (tid & 31) * 4;     // 0..124

    for (int k0 = 0; k0 < K; k0 += 8) {
        float4 av = *(const float4*)(Ab + (size_t)a_row * K + k0 + a_col4);
        As[a_col4+0][a_row] = av.x;
        As[a_col4+1][a_row] = av.y;
        As[a_col4+2][a_row] = av.z;
        As[a_col4+3][a_row] = av.w;
        float4 bv = *(const float4*)(Bb + (size_t)(k0 + b_row) * N + b_col4);
        *(float4*)&Bs[b_row][b_col4] = bv;
        __syncthreads();
#pragma unroll
        for (int kk = 0; kk < 8; kk++) {
            float a[8], b[8];
            float4 t0 = *(const float4*)&As[kk][ty*8];
            float4 t1 = *(const float4*)&As[kk][ty*8+4];
            a[0]=t0.x; a[1]=t0.y; a[2]=t0.z; a[3]=t0.w;
            a[4]=t1.x; a[5]=t1.y; a[6]=t1.z; a[7]=t1.w;
            float4 u0 = *(const float4*)&Bs[kk][tx*4];
            float4 u1 = *(const float4*)&Bs[kk][64 + tx*4];
            b[0]=u0.x; b[1]=u0.y; b[2]=u0.z; b[3]=u0.w;
            b[4]=u1.x; b[5]=u1.y; b[6]=u1.z; b[7]=u1.w;
#pragma unroll
            for (int i = 0; i < 8; i++)
#pragma unroll
                for (int j = 0; j < 8; j++)
                    acc[i][j] += a[i]*b[j];
        }
        __syncthreads();
    }

    // epilogue
#pragma unroll
    for (int i = 0; i < 8; i++) {
        int row = by*128 + ty*8 + i;
#pragma unroll
        for (int j = 0; j < 8; j++) {
            int col = bx*128 + ((j < 4) ? (tx*4 + j) : (64 + tx*4 + j - 4));
            float val = acc[i][j];
            if (bias)  val += bias[col];
            if (do_gelu) val = gelu_f(val);
            if (resid) val += resid[(size_t)row * N + col];
            C[(size_t)row * N + col] = val;
        }
    }
}

// ---------------- Flash attention (fp32, non-causal) ------------------------
// One block: 64 q-rows of one (b,h). 256 threads: 4 threads per row.
// K tiles of 32 rows. Online softmax; O accumulated in registers (16 cols/thread).
__global__ void flash_attn(const float* __restrict__ q, const float* __restrict__ k,
                           const float* __restrict__ v, float* __restrict__ ctx)
{
    __shared__ float Qs[64][68];
    __shared__ float Ks[32][68];
    __shared__ float Vs[32][68];
    __shared__ float Ps[64][36];

    int t = threadIdx.x;
    int qt = blockIdx.x;           // 0..31
    int bh = blockIdx.y;           // 0..31
    int b = bh >> 4, h = bh & 15;
    int q0 = qt * 64;

    const float* qb = q + ((size_t)b * SS) * DD + h * DHH;
    const float* kb = k + ((size_t)b * SS) * DD + h * DHH;
    const float* vb = v + ((size_t)b * SS) * DD + h * DHH;

    // load Q tile: 64 rows x 64 floats (1024 float4)
#pragma unroll
    for (int i = 0; i < 4; i++) {
        int idx4 = t + i*256;
        int r = idx4 >> 4, d4 = (idx4 & 15) * 4;
        float4 val = *(const float4*)(qb + (size_t)(q0 + r) * DD + d4);
        *(float4*)&Qs[r][d4] = val;
    }

    int r  = t >> 2;     // row 0..63
    int cg = t & 3;      // column group 0..3

    float m = -INFINITY, l = 0.f;
    float o[16];
#pragma unroll
    for (int i = 0; i < 16; i++) o[i] = 0.f;

    __syncthreads();

    for (int k0 = 0; k0 < SS; k0 += 32) {
        __syncthreads();   // previous PV done before overwriting K/V tiles
        // load K,V tiles: 32x64 each
#pragma unroll
        for (int i = 0; i < 8; i++) {
            int idx = t + i*256;
            int rr = idx >> 6, d = idx & 63;
            Ks[rr][d] = kb[(size_t)(k0 + rr) * DD + d];
            Vs[rr][d] = vb[(size_t)(k0 + rr) * DD + d];
        }
        __syncthreads();

        // scores: each thread: 8 key-cols c = cg + 4j
        float s[8];
#pragma unroll
        for (int j = 0; j < 8; j++) s[j] = 0.f;
#pragma unroll
        for (int d4 = 0; d4 < 16; d4++) {
            float4 qv = *(const float4*)&Qs[r][d4*4];
#pragma unroll
            for (int j = 0; j < 8; j++) {
                int c = cg + 4*j;
                float4 kv = *(const float4*)&Ks[c][d4*4];
                s[j] += qv.x*kv.x + qv.y*kv.y + qv.z*kv.z + qv.w*kv.w;
            }
        }
        float mloc = -INFINITY;
#pragma unroll
        for (int j = 0; j < 8; j++) {
            s[j] *= 0.125f;                 // 1/sqrt(64)
            mloc = fmaxf(mloc, s[j]);
        }
        mloc = fmaxf(mloc, __shfl_xor_sync(0xffffffffu, mloc, 1));
        mloc = fmaxf(mloc, __shfl_xor_sync(0xffffffffu, mloc, 2));
        float mnew = fmaxf(m, mloc);
        float corr = __expf(m - mnew);
        float psum = 0.f;
#pragma unroll
        for (int j = 0; j < 8; j++) {
            float p = __expf(s[j] - mnew);
            Ps[r][cg + 4*j] = p;
            psum += p;
        }
        psum += __shfl_xor_sync(0xffffffffu, psum, 1);
        psum += __shfl_xor_sync(0xffffffffu, psum, 2);
        l = l * corr + psum;
        m = mnew;
#pragma unroll
        for (int jj = 0; jj < 16; jj++) o[jj] *= corr;
        __syncwarp();   // Ps row written by 4 lanes of this warp

        // O += P @ V  (o col mapping: c = 16*(jj>>2) + cg*4 + (jj&3))
#pragma unroll
        for (int kk4 = 0; kk4 < 8; kk4++) {
            float4 pv = *(const float4*)&Ps[r][kk4*4];
            float pa[4] = {pv.x, pv.y, pv.z, pv.w};
#pragma unroll
            for (int kq = 0; kq < 4; kq++) {
                int kk = kk4*4 + kq;
#pragma unroll
                for (int ch = 0; ch < 4; ch++) {
                    float4 vv = *(const float4*)&Vs[kk][ch*16 + cg*4];
                    o[ch*4+0] += pa[kq]*vv.x;
                    o[ch*4+1] += pa[kq]*vv.y;
                    o[ch*4+2] += pa[kq]*vv.z;
                    o[ch*4+3] += pa[kq]*vv.w;
                }
            }
        }
    }

    float linv = 1.f / l;
    float* cb = ctx + ((size_t)(b*SS + q0 + r)) * DD + h * DHH;
#pragma unroll
    for (int jj = 0; jj < 16; jj++) {
        int c = 16*(jj >> 2) + cg*4 + (jj & 3);
        cb[c] = o[jj] * linv;
    }
}

// ---------------- launch ----------------------------------------------------
extern "C" void kernel_launch(void* const* d_in, const int* in_sizes, int n_in,
                              void* d_out, int out_size)
{
    (void)in_sizes; (void)n_in; (void)out_size;
    const float* x     = (const float*)d_in[0];
    const float* ln1_s = (const float*)d_in[1];
    const float* ln1_b = (const float*)d_in[2];
    const float* wk    = (const float*)d_in[3];
    const float* wq    = (const float*)d_in[4];
    const float* wv    = (const float*)d_in[5];
    const float* wo    = (const float*)d_in[6];
    const float* ln2_s = (const float*)d_in[7];
    const float* ln2_b = (const float*)d_in[8];
    const float* w1    = (const float*)d_in[9];
    const float* b1    = (const float*)d_in[10];
    const float* w2    = (const float*)d_in[11];
    const float* b2    = (const float*)d_in[12];
    float* out = (float*)d_out;

    float *h, *q, *k, *v, *ctx, *mlpin, *h2, *mid;
    cudaGetSymbolAddress((void**)&h,     g_h);
    cudaGetSymbolAddress((void**)&q,     g_q);
    cudaGetSymbolAddress((void**)&k,     g_k);
    cudaGetSymbolAddress((void**)&v,     g_v);
    cudaGetSymbolAddress((void**)&ctx,   g_ctx);
    cudaGetSymbolAddress((void**)&mlpin, g_mlpin);
    cudaGetSymbolAddress((void**)&h2,    g_h2);
    cudaGetSymbolAddress((void**)&mid,   g_mid);

    // 1. LN1
    ln_kernel<<<ROWS, 256>>>(x, ln1_s, ln1_b, h);
    // 2. QKV projections
    sgemm<<<dim3(DD/128, ROWS/128), 256>>>(h, wq, q, ROWS, DD, DD, nullptr, nullptr, 0);
    sgemm<<<dim3(DD/128, ROWS/128), 256>>>(h, wk, k, ROWS, DD, DD, nullptr, nullptr, 0);
    sgemm<<<dim3(DD/128, ROWS/128), 256>>>(h, wv, v, ROWS, DD, DD, nullptr, nullptr, 0);
    // 3. RoPE (in-place on q,k)
    rope_kernel<<<(BB*SS*HH*32)/256, 256>>>(q, k);
    // 4. Attention
    flash_attn<<<dim3(SS/64, BB*HH), 256>>>(q, k, v, ctx);
    // 5. WO projection + residual x
    sgemm<<<dim3(DD/128, ROWS/128), 256>>>(ctx, wo, mlpin, ROWS, DD, DD, nullptr, x, 0);
    // 6. LN2
    ln_kernel<<<ROWS, 256>>>(mlpin, ln2_s, ln2_b, h2);
    // 7. MLP up + bias + gelu
    sgemm<<<dim3(MM/128, ROWS/128), 256>>>(h2, w1, mid, ROWS, MM, DD, b1, nullptr, 1);
    // 8. MLP down + bias + residual -> out
    sgemm<<<dim3(DD/128, ROWS/128), 256>>>(mid, w2, out, ROWS, DD, MM, b2, mlpin, 0);
}

// round 3
// speedup vs baseline: 1.3477x; 1.3477x over previous
#include <cuda_runtime.h>
#include <cuda_bf16.h>
#include <math.h>
#include <stdint.h>

// Problem constants
#define BB 2
#define SS 2048
#define DD 1024
#define HH 16
#define DHH 64
#define MM 4096
#define ROWS (BB*SS)          // 4096
#define EPS 1e-6f

// HMMA GEMM tiling
#define BMH 128
#define BNH 128
#define BKH 32
#define LDSROW 80                 // bytes per smem row (32 bf16 + 8 pad)
#define TILEB (128*LDSROW)        // 10240 bytes per matrix tile
#define STAGE_H (4*TILEB)         // Ah, Al, Bh, Bl
#define HSMEM (2*STAGE_H)         // 81920

// ---------------- scratch (static device globals; no allocations) -----------
__device__ __nv_bfloat16 g_h_hi[ROWS*DD],  g_h_lo[ROWS*DD];
__device__ float         g_q[ROWS*DD], g_k[ROWS*DD], g_v[ROWS*DD];
__device__ __nv_bfloat16 g_ctx_hi[ROWS*DD], g_ctx_lo[ROWS*DD];
__device__ float         g_mlpin[ROWS*DD];
__device__ __nv_bfloat16 g_h2_hi[ROWS*DD], g_h2_lo[ROWS*DD];
__device__ __nv_bfloat16 g_mid_hi[ROWS*MM], g_mid_lo[ROWS*MM];
// transposed bf16 weights [N][K]
__device__ __nv_bfloat16 g_wqt_h[DD*DD], g_wqt_l[DD*DD];
__device__ __nv_bfloat16 g_wkt_h[DD*DD], g_wkt_l[DD*DD];
__device__ __nv_bfloat16 g_wvt_h[DD*DD], g_wvt_l[DD*DD];
__device__ __nv_bfloat16 g_wot_h[DD*DD], g_wot_l[DD*DD];
__device__ __nv_bfloat16 g_w1t_h[MM*DD], g_w1t_l[MM*DD];
__device__ __nv_bfloat16 g_w2t_h[DD*MM], g_w2t_l[DD*MM];

// ---------------- helpers ----------------------------------------------------
__device__ __forceinline__ uint32_t smem_to_u32(const void* p) {
    uint32_t a;
    asm("{ .reg .u64 t; cvta.to.shared.u64 t, %1; cvt.u32.u64 %0, t; }" : "=r"(a) : "l"(p));
    return a;
}
__device__ __forceinline__ void cp16(uint32_t saddr, const void* gaddr) {
    asm volatile("cp.async.cg.shared.global [%0], [%1], 16;" :: "r"(saddr), "l"(gaddr) : "memory");
}
__device__ __forceinline__ void cp_commit() {
    asm volatile("cp.async.commit_group;" ::: "memory");
}
__device__ __forceinline__ void cp_wait1() {
    asm volatile("cp.async.wait_group 1;" ::: "memory");
}
__device__ __forceinline__ void ldmx4(uint32_t* d, uint32_t addr) {
    asm volatile("ldmatrix.sync.aligned.m8n8.x4.shared.b16 {%0,%1,%2,%3}, [%4];"
                 : "=r"(d[0]), "=r"(d[1]), "=r"(d[2]), "=r"(d[3]) : "r"(addr));
}
__device__ __forceinline__ void mma_bf16(float* c, const uint32_t* a, const uint32_t* b) {
    asm volatile("mma.sync.aligned.m16n8k16.row.col.f32.bf16.bf16.f32 "
                 "{%0,%1,%2,%3}, {%4,%5,%6,%7}, {%8,%9}, {%0,%1,%2,%3};"
                 : "+f"(c[0]), "+f"(c[1]), "+f"(c[2]), "+f"(c[3])
                 : "r"(a[0]), "r"(a[1]), "r"(a[2]), "r"(a[3]), "r"(b[0]), "r"(b[1]));
}
__device__ __forceinline__ void split_bf16(float v, __nv_bfloat16& h, __nv_bfloat16& l) {
    h = __float2bfloat16(v);
    l = __float2bfloat16(v - __bfloat162float(h));
}
__device__ __forceinline__ float gelu_f(float x) {
    float x3 = x*x*x;
    float t = tanhf(0.7978845608028654f * (x + 0.044715f * x3));
    return 0.5f * x * (1.f + t);
}

// ---------------- LayerNorm -> bf16 hi/lo ------------------------------------
__global__ void ln_bf16(const float* __restrict__ x,
                        const float* __restrict__ gamma,
                        const float* __restrict__ beta,
                        __nv_bfloat16* __restrict__ oh,
                        __nv_bfloat16* __restrict__ ol)
{
    __shared__ float red0[8], red1[8];
    int row = blockIdx.x;
    int t = threadIdx.x;
    const float* xr = x + (size_t)row * DD;
    float v[4];
    float sum = 0.f, sq = 0.f;
#pragma unroll
    for (int i = 0; i < 4; i++) { v[i] = xr[t + i*256]; sum += v[i]; sq += v[i]*v[i]; }
#pragma unroll
    for (int o = 16; o; o >>= 1) {
        sum += __shfl_xor_sync(0xffffffffu, sum, o);
        sq  += __shfl_xor_sync(0xffffffffu, sq,  o);
    }
    if ((t & 31) == 0) { red0[t >> 5] = sum; red1[t >> 5] = sq; }
    __syncthreads();
    if (t < 32) {
        float s = (t < 8) ? red0[t] : 0.f;
        float q = (t < 8) ? red1[t] : 0.f;
#pragma unroll
        for (int o = 4; o; o >>= 1) {
            s += __shfl_xor_sync(0xffffffffu, s, o);
            q += __shfl_xor_sync(0xffffffffu, q, o);
        }
        if (t == 0) { red0[0] = s; red1[0] = q; }
    }
    __syncthreads();
    float mean = red0[0] * (1.f / (float)DD);
    float var  = red1[0] * (1.f / (float)DD) - mean*mean;
    float rstd = rsqrtf(var + EPS);
    size_t base = (size_t)row * DD;
#pragma unroll
    for (int i = 0; i < 4; i++) {
        int c = t + i*256;
        float val = (v[i] - mean) * rstd * gamma[c] + beta[c];
        __nv_bfloat16 hh, ll; split_bf16(val, hh, ll);
        oh[base + c] = hh; ol[base + c] = ll;
    }
}

// ---------------- weight transpose + split: W[K][N] -> T[N][K] hi/lo ---------
__global__ void tconv(const float* __restrict__ W,
                      __nv_bfloat16* __restrict__ Th, __nv_bfloat16* __restrict__ Tl,
                      int K, int N)
{
    __shared__ float t[32][33];
    int n0 = blockIdx.x * 32, k0 = blockIdx.y * 32;
    int tx = threadIdx.x, ty = threadIdx.y;   // 32 x 8
#pragma unroll
    for (int j = 0; j < 32; j += 8)
        t[ty + j][tx] = W[(size_t)(k0 + ty + j) * N + n0 + tx];
    __syncthreads();
#pragma unroll
    for (int j = 0; j < 32; j += 8) {
        float v = t[tx][ty + j];
        __nv_bfloat16 hh, ll; split_bf16(v, hh, ll);
        size_t o = (size_t)(n0 + ty + j) * K + k0 + tx;
        Th[o] = hh; Tl[o] = ll;
    }
}

// ---------------- RoPE -------------------------------------------------------
__global__ void rope_kernel(float* __restrict__ q, float* __restrict__ k)
{
    int idx = blockIdx.x * 256 + threadIdx.x;
    int i = idx & 31;
    int h = (idx >> 5) & 15;
    int s = (idx >> 9) & 2047;
    int b = idx >> 20;
    float freq = powf(10000.0f, -((float)(2*i)) / 64.0f);
    float ang = (float)s * freq;
    float sn, cs;
    sincosf(ang, &sn, &cs);
    size_t base = ((size_t)(b*SS + s)) * DD + h*DHH + 2*i;
    float a0 = q[base], b0 = q[base+1];
    q[base]   = a0*cs - b0*sn;
    q[base+1] = a0*sn + b0*cs;
    a0 = k[base]; b0 = k[base+1];
    k[base]   = a0*cs - b0*sn;
    k[base+1] = a0*sn + b0*cs;
}

// ---------------- HMMA bf16x3 GEMM ------------------------------------------
// C[M,N] = A[M,K] @ B^T, Bt is [N][K] row-major. All operands bf16 hi/lo.
// modes: 0 C=acc; 1 C=acc+resid; 2 Oh/Ol=split(gelu(acc+bias)); 3 C=acc+bias+resid
__global__ __launch_bounds__(256, 1)
void gemm_hmma(const __nv_bfloat16* __restrict__ Ah, const __nv_bfloat16* __restrict__ Al,
               const __nv_bfloat16* __restrict__ Bh, const __nv_bfloat16* __restrict__ Bl,
               float* __restrict__ C, int Ndim, int Kdim,
               const float* __restrict__ bias, const float* __restrict__ resid,
               __nv_bfloat16* __restrict__ Oh, __nv_bfloat16* __restrict__ Ol,
               int mode)
{
    extern __shared__ char hs[];
    uint32_t sb = smem_to_u32(hs);
    int tid = threadIdx.x, wid = tid >> 5, lane = tid & 31;
    int bx = blockIdx.x, by = blockIdx.y;

    const __nv_bfloat16* Ahb = Ah + (size_t)by * BMH * Kdim;
    const __nv_bfloat16* Alb = Al + (size_t)by * BMH * Kdim;
    const __nv_bfloat16* Bhb = Bh + (size_t)bx * BNH * Kdim;
    const __nv_bfloat16* Blb = Bl + (size_t)bx * BNH * Kdim;

    int nch = Kdim / BKH;

    // chunk loader: 128 rows x 32 bf16 per matrix, 4x16B per row
    auto load_chunk = [&](int c, int s) {
        int k0 = c * BKH;
        uint32_t st = sb + s * STAGE_H;
#pragma unroll
        for (int i = tid; i < 512; i += 256) {
            int row = i >> 2, seg = i & 3;
            uint32_t so = st + row * LDSROW + seg * 16;
            size_t go = (size_t)row * Kdim + k0 + seg * 8;
            cp16(so,             Ahb + go);
            cp16(so + TILEB,     Alb + go);
            cp16(so + 2*TILEB,   Bhb + go);
            cp16(so + 3*TILEB,   Blb + go);
        }
    };

    float acc[4][4][4];
#pragma unroll
    for (int i = 0; i < 4; i++)
#pragma unroll
        for (int j = 0; j < 4; j++)
#pragma unroll
            for (int r = 0; r < 4; r++) acc[i][j][r] = 0.f;

    int wm = (wid & 1) * 64;       // warp m offset
    int wn = (wid >> 1) * 32;      // warp n offset

    load_chunk(0, 0);
    cp_commit();

    for (int c = 0; c < nch; c++) {
        int s = c & 1;
        if (c + 1 < nch) load_chunk(c + 1, s ^ 1);
        cp_commit();
        cp_wait1();
        __syncthreads();

        uint32_t st = sb + s * STAGE_H;
#pragma unroll
        for (int ks = 0; ks < 2; ks++) {
            int colb = ks * 16 + (lane >> 4) * 8;     // element offset in row
            uint32_t ah[4][4], al[4][4], bh[4][2], bl[4][2];
#pragma unroll
            for (int mf = 0; mf < 4; mf++) {
                int r = wm + mf * 16 + (lane & 15);
                uint32_t ad = st + r * LDSROW + colb * 2;
                ldmx4(ah[mf], ad);
                ldmx4(al[mf], ad + TILEB);
            }
#pragma unroll
            for (int nf2 = 0; nf2 < 2; nf2++) {
                int r = wn + nf2 * 16 + ((lane >> 3) & 1) * 8 + (lane & 7);
                uint32_t bd = st + 2*TILEB + r * LDSROW + colb * 2;
                uint32_t tb[4];
                ldmx4(tb, bd);
                bh[nf2*2][0] = tb[0]; bh[nf2*2][1] = tb[2];
                bh[nf2*2+1][0] = tb[1]; bh[nf2*2+1][1] = tb[3];
                ldmx4(tb, bd + TILEB);
                bl[nf2*2][0] = tb[0]; bl[nf2*2][1] = tb[2];
                bl[nf2*2+1][0] = tb[1]; bl[nf2*2+1][1] = tb[3];
            }
#pragma unroll
            for (int mf = 0; mf < 4; mf++)
#pragma unroll
                for (int nf = 0; nf < 4; nf++) {
                    mma_bf16(acc[mf][nf], ah[mf], bh[nf]);
                    mma_bf16(acc[mf][nf], ah[mf], bl[nf]);
                    mma_bf16(acc[mf][nf], al[mf], bh[nf]);
                }
        }
        __syncthreads();
    }

    // epilogue: frag (mf, nf): rows by*128 + wm + mf*16 + {g, g+8}, cols bx*128 + wn + nf*8 + q*2
    int g = lane >> 2, qd = lane & 3;
#pragma unroll
    for (int mf = 0; mf < 4; mf++) {
#pragma unroll
        for (int half = 0; half < 2; half++) {
            int grow = by * BMH + wm + mf * 16 + g + half * 8;
#pragma unroll
            for (int nf = 0; nf < 4; nf++) {
                int gcol = bx * BNH + wn + nf * 8 + qd * 2;
                float v0 = acc[mf][nf][half*2 + 0];
                float v1 = acc[mf][nf][half*2 + 1];
                size_t o = (size_t)grow * Ndim + gcol;
                if (mode == 0) {
                    C[o] = v0; C[o+1] = v1;
                } else if (mode == 1) {
                    C[o] = v0 + resid[o]; C[o+1] = v1 + resid[o+1];
                } else if (mode == 2) {
                    float g0 = gelu_f(v0 + bias[gcol]);
                    float g1 = gelu_f(v1 + bias[gcol+1]);
                    __nv_bfloat16 hh, ll;
                    split_bf16(g0, hh, ll); Oh[o] = hh; Ol[o] = ll;
                    split_bf16(g1, hh, ll); Oh[o+1] = hh; Ol[o+1] = ll;
                } else {
                    C[o]   = v0 + bias[gcol]   + resid[o];
                    C[o+1] = v1 + bias[gcol+1] + resid[o+1];
                }
            }
        }
    }
}

// ---------------- Flash attention (fp32) -> ctx bf16 hi/lo -------------------
__global__ void flash_attn(const float* __restrict__ q, const float* __restrict__ k,
                           const float* __restrict__ v,
                           __nv_bfloat16* __restrict__ ctx_hi,
                           __nv_bfloat16* __restrict__ ctx_lo)
{
    __shared__ float Qs[64][68];
    __shared__ float Ks[32][68];
    __shared__ float Vs[32][68];
    __shared__ float Ps[64][36];

    int t = threadIdx.x;
    int qt = blockIdx.x;
    int bh = blockIdx.y;
    int b = bh >> 4, h = bh & 15;
    int q0 = qt * 64;

    const float* qb = q + ((size_t)b * SS) * DD + h * DHH;
    const float* kb = k + ((size_t)b * SS) * DD + h * DHH;
    const float* vb = v + ((size_t)b * SS) * DD + h * DHH;

#pragma unroll
    for (int i = 0; i < 4; i++) {
        int idx4 = t + i*256;
        int r = idx4 >> 4, d4 = (idx4 & 15) * 4;
        float4 val = *(const float4*)(qb + (size_t)(q0 + r) * DD + d4);
        *(float4*)&Qs[r][d4] = val;
    }

    int r  = t >> 2;
    int cg = t & 3;

    float m = -INFINITY, l = 0.f;
    float o[16];
#pragma unroll
    for (int i = 0; i < 16; i++) o[i] = 0.f;

    __syncthreads();

    for (int k0 = 0; k0 < SS; k0 += 32) {
        __syncthreads();
#pragma unroll
        for (int i = 0; i < 8; i++) {
            int idx = t + i*256;
            int rr = idx >> 6, d = idx & 63;
            Ks[rr][d] = kb[(size_t)(k0 + rr) * DD + d];
            Vs[rr][d] = vb[(size_t)(k0 + rr) * DD + d];
        }
        __syncthreads();

        float s[8];
#pragma unroll
        for (int j = 0; j < 8; j++) s[j] = 0.f;
#pragma unroll
        for (int d4 = 0; d4 < 16; d4++) {
            float4 qv = *(const float4*)&Qs[r][d4*4];
#pragma unroll
            for (int j = 0; j < 8; j++) {
                int c = cg + 4*j;
                float4 kv = *(const float4*)&Ks[c][d4*4];
                s[j] += qv.x*kv.x + qv.y*kv.y + qv.z*kv.z + qv.w*kv.w;
            }
        }
        float mloc = -INFINITY;
#pragma unroll
        for (int j = 0; j < 8; j++) { s[j] *= 0.125f; mloc = fmaxf(mloc, s[j]); }
        mloc = fmaxf(mloc, __shfl_xor_sync(0xffffffffu, mloc, 1));
        mloc = fmaxf(mloc, __shfl_xor_sync(0xffffffffu, mloc, 2));
        float mnew = fmaxf(m, mloc);
        float corr = __expf(m - mnew);
        float psum = 0.f;
#pragma unroll
        for (int j = 0; j < 8; j++) {
            float p = __expf(s[j] - mnew);
            Ps[r][cg + 4*j] = p;
            psum += p;
        }
        psum += __shfl_xor_sync(0xffffffffu, psum, 1);
        psum += __shfl_xor_sync(0xffffffffu, psum, 2);
        l = l * corr + psum;
        m = mnew;
#pragma unroll
        for (int jj = 0; jj < 16; jj++) o[jj] *= corr;
        __syncwarp();

#pragma unroll
        for (int kk4 = 0; kk4 < 8; kk4++) {
            float4 pv = *(const float4*)&Ps[r][kk4*4];
            float pa[4] = {pv.x, pv.y, pv.z, pv.w};
#pragma unroll
            for (int kq = 0; kq < 4; kq++) {
                int kk = kk4*4 + kq;
#pragma unroll
                for (int ch = 0; ch < 4; ch++) {
                    float4 vv = *(const float4*)&Vs[kk][ch*16 + cg*4];
                    o[ch*4+0] += pa[kq]*vv.x;
                    o[ch*4+1] += pa[kq]*vv.y;
                    o[ch*4+2] += pa[kq]*vv.z;
                    o[ch*4+3] += pa[kq]*vv.w;
                }
            }
        }
    }

    float linv = 1.f / l;
    size_t obase = ((size_t)(b*SS + q0 + r)) * DD + h * DHH;
#pragma unroll
    for (int jj = 0; jj < 16; jj++) {
        int c = 16*(jj >> 2) + cg*4 + (jj & 3);
        float val = o[jj] * linv;
        __nv_bfloat16 hh, ll; split_bf16(val, hh, ll);
        ctx_hi[obase + c] = hh; ctx_lo[obase + c] = ll;
    }
}

// ---------------- launch ----------------------------------------------------
extern "C" void kernel_launch(void* const* d_in, const int* in_sizes, int n_in,
                              void* d_out, int out_size)
{
    (void)in_sizes; (void)n_in; (void)out_size;
    const float* x     = (const float*)d_in[0];
    const float* ln1_s = (const float*)d_in[1];
    const float* ln1_b = (const float*)d_in[2];
    const float* wk    = (const float*)d_in[3];
    const float* wq    = (const float*)d_in[4];
    const float* wv    = (const float*)d_in[5];
    const float* wo    = (const float*)d_in[6];
    const float* ln2_s = (const float*)d_in[7];
    const float* ln2_b = (const float*)d_in[8];
    const float* w1    = (const float*)d_in[9];
    const float* b1    = (const float*)d_in[10];
    const float* w2    = (const float*)d_in[11];
    const float* b2    = (const float*)d_in[12];
    float* out = (float*)d_out;

    static int configured = 0;
    if (!configured) {
        cudaFuncSetAttribute(gemm_hmma, cudaFuncAttributeMaxDynamicSharedMemorySize, HSMEM);
        configured = 1;
    }

    __nv_bfloat16 *h_hi, *h_lo, *ctx_hi, *ctx_lo, *h2_hi, *h2_lo, *mid_hi, *mid_lo;
    __nv_bfloat16 *wqt_h, *wqt_l, *wkt_h, *wkt_l, *wvt_h, *wvt_l, *wot_h, *wot_l;
    __nv_bfloat16 *w1t_h, *w1t_l, *w2t_h, *w2t_l;
    float *q, *k, *v, *mlpin;
    cudaGetSymbolAddress((void**)&h_hi,  g_h_hi);   cudaGetSymbolAddress((void**)&h_lo,  g_h_lo);
    cudaGetSymbolAddress((void**)&q,     g_q);      cudaGetSymbolAddress((void**)&k,     g_k);
    cudaGetSymbolAddress((void**)&v,     g_v);
    cudaGetSymbolAddress((void**)&ctx_hi,g_ctx_hi); cudaGetSymbolAddress((void**)&ctx_lo,g_ctx_lo);
    cudaGetSymbolAddress((void**)&mlpin, g_mlpin);
    cudaGetSymbolAddress((void**)&h2_hi, g_h2_hi);  cudaGetSymbolAddress((void**)&h2_lo, g_h2_lo);
    cudaGetSymbolAddress((void**)&mid_hi,g_mid_hi); cudaGetSymbolAddress((void**)&mid_lo,g_mid_lo);
    cudaGetSymbolAddress((void**)&wqt_h, g_wqt_h);  cudaGetSymbolAddress((void**)&wqt_l, g_wqt_l);
    cudaGetSymbolAddress((void**)&wkt_h, g_wkt_h);  cudaGetSymbolAddress((void**)&wkt_l, g_wkt_l);
    cudaGetSymbolAddress((void**)&wvt_h, g_wvt_h);  cudaGetSymbolAddress((void**)&wvt_l, g_wvt_l);
    cudaGetSymbolAddress((void**)&wot_h, g_wot_h);  cudaGetSymbolAddress((void**)&wot_l, g_wot_l);
    cudaGetSymbolAddress((void**)&w1t_h, g_w1t_h);  cudaGetSymbolAddress((void**)&w1t_l, g_w1t_l);
    cudaGetSymbolAddress((void**)&w2t_h, g_w2t_h);  cudaGetSymbolAddress((void**)&w2t_l, g_w2t_l);

    dim3 tb(32, 8);
    tconv<<<dim3(DD/32, DD/32), tb>>>(wq, wqt_h, wqt_l, DD, DD);
    tconv<<<dim3(DD/32, DD/32), tb>>>(wk, wkt_h, wkt_l, DD, DD);
    tconv<<<dim3(DD/32, DD/32), tb>>>(wv, wvt_h, wvt_l, DD, DD);
    tconv<<<dim3(DD/32, DD/32), tb>>>(wo, wot_h, wot_l, DD, DD);
    tconv<<<dim3(MM/32, DD/32), tb>>>(w1, w1t_h, w1t_l, DD, MM);
    tconv<<<dim3(DD/32, MM/32), tb>>>(w2, w2t_h, w2t_l, MM, DD);

    // 1. LN1 -> bf16 hi/lo
    ln_bf16<<<ROWS, 256>>>(x, ln1_s, ln1_b, h_hi, h_lo);

    // 2. QKV projections (fp32 out)
    dim3 gDD(DD/BNH, ROWS/BMH);
    gemm_hmma<<<gDD, 256, HSMEM>>>(h_hi, h_lo, wqt_h, wqt_l, q, DD, DD,
                                   nullptr, nullptr, nullptr, nullptr, 0);
    gemm_hmma<<<gDD, 256, HSMEM>>>(h_hi, h_lo, wkt_h, wkt_l, k, DD, DD,
                                   nullptr, nullptr, nullptr, nullptr, 0);
    gemm_hmma<<<gDD, 256, HSMEM>>>(h_hi, h_lo, wvt_h, wvt_l, v, DD, DD,
                                   nullptr, nullptr, nullptr, nullptr, 0);

    // 3. RoPE
    rope_kernel<<<(BB*SS*HH*32)/256, 256>>>(q, k);

    // 4. Attention -> ctx bf16 hi/lo
    flash_attn<<<dim3(SS/64, BB*HH), 256>>>(q, k, v, ctx_hi, ctx_lo);

    // 5. WO projection + residual x -> mlpin (fp32)
    gemm_hmma<<<gDD, 256, HSMEM>>>(ctx_hi, ctx_lo, wot_h, wot_l, mlpin, DD, DD,
                                   nullptr, x, nullptr, nullptr, 1);

    // 6. LN2 -> bf16 hi/lo
    ln_bf16<<<ROWS, 256>>>(mlpin, ln2_s, ln2_b, h2_hi, h2_lo);

    // 7. MLP up: gelu(h2@w1+b1) -> mid bf16 hi/lo
    gemm_hmma<<<dim3(MM/BNH, ROWS/BMH), 256, HSMEM>>>(h2_hi, h2_lo, w1t_h, w1t_l,
                                   nullptr, MM, DD, b1, nullptr, mid_hi, mid_lo, 2);

    // 8. MLP down + bias + residual -> out (fp32)
    gemm_hmma<<<gDD, 256, HSMEM>>>(mid_hi, mid_lo, w2t_h, w2t_l, out, DD, MM,
                                   b2, mlpin, nullptr, nullptr, 3);
}

// round 6
// speedup vs baseline: 2.6959x; 2.0004x over previous
#include <cuda_runtime.h>
#include <cuda_bf16.h>
#include <math.h>
#include <stdint.h>
#include <string.h>

// Problem constants
#define BB 2
#define SS 2048
#define DD 1024
#define HH 16
#define DHH 64
#define MM 4096
#define ROWS (BB*SS)          // 4096
#define EPS 1e-6f

// HMMA GEMM tiling
#define BMH 128
#define BNH 128
#define BKH 32
#define LDSROW 80                 // bytes per smem row (32 bf16 + 8 pad)
#define TILEB (128*LDSROW)        // 10240 bytes per matrix tile
#define STAGE_H (4*TILEB)         // Ah, Al, Bh, Bl
#define HSMEM (2*STAGE_H)         // 81920

// Flash attention tiling
#define AQT 128                   // q rows per block
#define AKT 64                    // keys per tile
#define ASTR 144                  // smem row stride bytes (64 bf16 + 8 pad)
#define AQH_OFF 0
#define AQL_OFF 18432
#define AST0 36864
#define ASTAGE 36864              // Kh,Kl,Vh,Vl each 64*144=9216
#define ASMEM 110592

// ---------------- scratch (static device globals; no allocations) -----------
__device__ __nv_bfloat16 g_h_hi[ROWS*DD],  g_h_lo[ROWS*DD];
__device__ float         g_q[ROWS*DD], g_k[ROWS*DD];
__device__ __nv_bfloat16 g_qh[ROWS*DD], g_ql[ROWS*DD];
__device__ __nv_bfloat16 g_kh[ROWS*DD], g_kl[ROWS*DD];
__device__ __nv_bfloat16 g_vh[ROWS*DD], g_vl[ROWS*DD];
__device__ __nv_bfloat16 g_ctx_hi[ROWS*DD], g_ctx_lo[ROWS*DD];
__device__ float         g_mlpin[ROWS*DD];
__device__ __nv_bfloat16 g_h2_hi[ROWS*DD], g_h2_lo[ROWS*DD];
__device__ __nv_bfloat16 g_mid_hi[ROWS*MM], g_mid_lo[ROWS*MM];
// transposed bf16 weights [N][K]
__device__ __nv_bfloat16 g_wqt_h[DD*DD], g_wqt_l[DD*DD];
__device__ __nv_bfloat16 g_wkt_h[DD*DD], g_wkt_l[DD*DD];
__device__ __nv_bfloat16 g_wvt_h[DD*DD], g_wvt_l[DD*DD];
__device__ __nv_bfloat16 g_wot_h[DD*DD], g_wot_l[DD*DD];
__device__ __nv_bfloat16 g_w1t_h[MM*DD], g_w1t_l[MM*DD];
__device__ __nv_bfloat16 g_w2t_h[DD*MM], g_w2t_l[DD*MM];

// ---------------- helpers ----------------------------------------------------
__device__ __forceinline__ uint32_t smem_to_u32(const void* p) {
    uint32_t a;
    asm("{ .reg .u64 t; cvta.to.shared.u64 t, %1; cvt.u32.u64 %0, t; }" : "=r"(a) : "l"(p));
    return a;
}
__device__ __forceinline__ void cp16(uint32_t saddr, const void* gaddr) {
    asm volatile("cp.async.cg.shared.global [%0], [%1], 16;" :: "r"(saddr), "l"(gaddr) : "memory");
}
__device__ __forceinline__ void cp_commit() {
    asm volatile("cp.async.commit_group;" ::: "memory");
}
__device__ __forceinline__ void cp_wait1() {
    asm volatile("cp.async.wait_group 1;" ::: "memory");
}
__device__ __forceinline__ void ldmx4(uint32_t* d, uint32_t addr) {
    asm volatile("ldmatrix.sync.aligned.m8n8.x4.shared.b16 {%0,%1,%2,%3}, [%4];"
                 : "=r"(d[0]), "=r"(d[1]), "=r"(d[2]), "=r"(d[3]) : "r"(addr));
}
__device__ __forceinline__ void ldmx4t(uint32_t* d, uint32_t addr) {
    asm volatile("ldmatrix.sync.aligned.m8n8.x4.trans.shared.b16 {%0,%1,%2,%3}, [%4];"
                 : "=r"(d[0]), "=r"(d[1]), "=r"(d[2]), "=r"(d[3]) : "r"(addr));
}
__device__ __forceinline__ void mma_bf16(float* c, const uint32_t* a, const uint32_t* b) {
    asm volatile("mma.sync.aligned.m16n8k16.row.col.f32.bf16.bf16.f32 "
                 "{%0,%1,%2,%3}, {%4,%5,%6,%7}, {%8,%9}, {%0,%1,%2,%3};"
                 : "+f"(c[0]), "+f"(c[1]), "+f"(c[2]), "+f"(c[3])
                 : "r"(a[0]), "r"(a[1]), "r"(a[2]), "r"(a[3]), "r"(b[0]), "r"(b[1]));
}
__device__ __forceinline__ void split_bf16(float v, __nv_bfloat16& h, __nv_bfloat16& l) {
    h = __float2bfloat16(v);
    l = __float2bfloat16(v - __bfloat162float(h));
}
__device__ __forceinline__ uint32_t pack_bf2(float a, float b) {
    __nv_bfloat162 t = __floats2bfloat162_rn(a, b);   // .x=a (low), .y=b (high)
    return *reinterpret_cast<uint32_t*>(&t);
}
__device__ __forceinline__ float gelu_f(float x) {
    float x3 = x*x*x;
    float t = tanhf(0.7978845608028654f * (x + 0.044715f * x3));
    return 0.5f * x * (1.f + t);
}

// ---------------- LayerNorm -> bf16 hi/lo ------------------------------------
__global__ void ln_bf16(const float* __restrict__ x,
                        const float* __restrict__ gamma,
                        const float* __restrict__ beta,
                        __nv_bfloat16* __restrict__ oh,
                        __nv_bfloat16* __restrict__ ol)
{
    __shared__ float red0[8], red1[8];
    int row = blockIdx.x;
    int t = threadIdx.x;
    const float* xr = x + (size_t)row * DD;
    float v[4];
    float sum = 0.f, sq = 0.f;
#pragma unroll
    for (int i = 0; i < 4; i++) { v[i] = xr[t + i*256]; sum += v[i]; sq += v[i]*v[i]; }
#pragma unroll
    for (int o = 16; o; o >>= 1) {
        sum += __shfl_xor_sync(0xffffffffu, sum, o);
        sq  += __shfl_xor_sync(0xffffffffu, sq,  o);
    }
    if ((t & 31) == 0) { red0[t >> 5] = sum; red1[t >> 5] = sq; }
    __syncthreads();
    if (t < 32) {
        float s = (t < 8) ? red0[t] : 0.f;
        float q = (t < 8) ? red1[t] : 0.f;
#pragma unroll
        for (int o = 4; o; o >>= 1) {
            s += __shfl_xor_sync(0xffffffffu, s, o);
            q += __shfl_xor_sync(0xffffffffu, q, o);
        }
        if (t == 0) { red0[0] = s; red1[0] = q; }
    }
    __syncthreads();
    float mean = red0[0] * (1.f / (float)DD);
    float var  = red1[0] * (1.f / (float)DD) - mean*mean;
    float rstd = rsqrtf(var + EPS);
    size_t base = (size_t)row * DD;
#pragma unroll
    for (int i = 0; i < 4; i++) {
        int c = t + i*256;
        float val = (v[i] - mean) * rstd * gamma[c] + beta[c];
        __nv_bfloat16 hh, ll; split_bf16(val, hh, ll);
        oh[base + c] = hh; ol[base + c] = ll;
    }
}

// ---------------- weight transpose + split: W[K][N] -> T[N][K] hi/lo ---------
__global__ void tconv(const float* __restrict__ W,
                      __nv_bfloat16* __restrict__ Th, __nv_bfloat16* __restrict__ Tl,
                      int K, int N)
{
    __shared__ float t[32][33];
    int n0 = blockIdx.x * 32, k0 = blockIdx.y * 32;
    int tx = threadIdx.x, ty = threadIdx.y;   // 32 x 8
#pragma unroll
    for (int j = 0; j < 32; j += 8)
        t[ty + j][tx] = W[(size_t)(k0 + ty + j) * N + n0 + tx];
    __syncthreads();
#pragma unroll
    for (int j = 0; j < 32; j += 8) {
        float v = t[tx][ty + j];
        __nv_bfloat16 hh, ll; split_bf16(v, hh, ll);
        size_t o = (size_t)(n0 + ty + j) * K + k0 + tx;
        Th[o] = hh; Tl[o] = ll;
    }
}

// ---------------- RoPE + split to bf16 hi/lo (q scaled by 1/8, exact) --------
__global__ void rope_split(const float* __restrict__ q, const float* __restrict__ k,
                           __nv_bfloat16* __restrict__ qh, __nv_bfloat16* __restrict__ ql,
                           __nv_bfloat16* __restrict__ kh, __nv_bfloat16* __restrict__ kl)
{
    int idx = blockIdx.x * 256 + threadIdx.x;
    int i = idx & 31;
    int h = (idx >> 5) & 15;
    int s = (idx >> 9) & 2047;
    int b = idx >> 20;
    float freq = powf(10000.0f, -((float)(2*i)) / 64.0f);
    float ang = (float)s * freq;
    float sn, cs;
    sincosf(ang, &sn, &cs);
    size_t base = ((size_t)(b*SS + s)) * DD + h*DHH + 2*i;
    float a0 = q[base], b0 = q[base+1];
    float r0 = (a0*cs - b0*sn) * 0.125f;   // fold 1/sqrt(64): exact pow2 scale
    float r1 = (a0*sn + b0*cs) * 0.125f;
    __nv_bfloat16 hh, ll;
    split_bf16(r0, hh, ll); qh[base] = hh;   ql[base] = ll;
    split_bf16(r1, hh, ll); qh[base+1] = hh; ql[base+1] = ll;
    a0 = k[base]; b0 = k[base+1];
    r0 = a0*cs - b0*sn;
    r1 = a0*sn + b0*cs;
    split_bf16(r0, hh, ll); kh[base] = hh;   kl[base] = ll;
    split_bf16(r1, hh, ll); kh[base+1] = hh; kl[base+1] = ll;
}

// ---------------- HMMA bf16x3 GEMM ------------------------------------------
// C[M,N] = A[M,K] @ B^T, Bt is [N][K] row-major. All operands bf16 hi/lo.
// modes: 0 C=acc; 1 C=acc+resid; 2 Oh/Ol=split(gelu(acc+bias)); 3 C=acc+bias+resid;
//        4 Oh/Ol=split(acc)
__global__ __launch_bounds__(256, 1)
void gemm_hmma(const __nv_bfloat16* __restrict__ Ah, const __nv_bfloat16* __restrict__ Al,
               const __nv_bfloat16* __restrict__ Bh, const __nv_bfloat16* __restrict__ Bl,
               float* __restrict__ C, int Ndim, int Kdim,
               const float* __restrict__ bias, const float* __restrict__ resid,
               __nv_bfloat16* __restrict__ Oh, __nv_bfloat16* __restrict__ Ol,
               int mode)
{
    extern __shared__ char hs[];
    uint32_t sb = smem_to_u32(hs);
    int tid = threadIdx.x, wid = tid >> 5, lane = tid & 31;
    int bx = blockIdx.x, by = blockIdx.y;

    const __nv_bfloat16* Ahb = Ah + (size_t)by * BMH * Kdim;
    const __nv_bfloat16* Alb = Al + (size_t)by * BMH * Kdim;
    const __nv_bfloat16* Bhb = Bh + (size_t)bx * BNH * Kdim;
    const __nv_bfloat16* Blb = Bl + (size_t)bx * BNH * Kdim;

    int nch = Kdim / BKH;

    auto load_chunk = [&](int c, int s) {
        int k0 = c * BKH;
        uint32_t st = sb + s * STAGE_H;
#pragma unroll
        for (int i = tid; i < 512; i += 256) {
            int row = i >> 2, seg = i & 3;
            uint32_t so = st + row * LDSROW + seg * 16;
            size_t go = (size_t)row * Kdim + k0 + seg * 8;
            cp16(so,             Ahb + go);
            cp16(so + TILEB,     Alb + go);
            cp16(so + 2*TILEB,   Bhb + go);
            cp16(so + 3*TILEB,   Blb + go);
        }
    };

    float acc[4][4][4];
#pragma unroll
    for (int i = 0; i < 4; i++)
#pragma unroll
        for (int j = 0; j < 4; j++)
#pragma unroll
            for (int r = 0; r < 4; r++) acc[i][j][r] = 0.f;

    int wm = (wid & 1) * 64;
    int wn = (wid >> 1) * 32;

    load_chunk(0, 0);
    cp_commit();

    for (int c = 0; c < nch; c++) {
        int s = c & 1;
        if (c + 1 < nch) load_chunk(c + 1, s ^ 1);
        cp_commit();
        cp_wait1();
        __syncthreads();

        uint32_t st = sb + s * STAGE_H;
#pragma unroll
        for (int ks = 0; ks < 2; ks++) {
            int colb = ks * 16 + (lane >> 4) * 8;
            uint32_t ah[4][4], al[4][4], bh[4][2], bl[4][2];
#pragma unroll
            for (int mf = 0; mf < 4; mf++) {
                int r = wm + mf * 16 + (lane & 15);
                uint32_t ad = st + r * LDSROW + colb * 2;
                ldmx4(ah[mf], ad);
                ldmx4(al[mf], ad + TILEB);
            }
#pragma unroll
            for (int nf2 = 0; nf2 < 2; nf2++) {
                int r = wn + nf2 * 16 + ((lane >> 3) & 1) * 8 + (lane & 7);
                uint32_t bd = st + 2*TILEB + r * LDSROW + colb * 2;
                uint32_t tb[4];
                ldmx4(tb, bd);
                bh[nf2*2][0] = tb[0]; bh[nf2*2][1] = tb[2];
                bh[nf2*2+1][0] = tb[1]; bh[nf2*2+1][1] = tb[3];
                ldmx4(tb, bd + TILEB);
                bl[nf2*2][0] = tb[0]; bl[nf2*2][1] = tb[2];
                bl[nf2*2+1][0] = tb[1]; bl[nf2*2+1][1] = tb[3];
            }
#pragma unroll
            for (int mf = 0; mf < 4; mf++)
#pragma unroll
                for (int nf = 0; nf < 4; nf++) {
                    mma_bf16(acc[mf][nf], ah[mf], bh[nf]);
                    mma_bf16(acc[mf][nf], ah[mf], bl[nf]);
                    mma_bf16(acc[mf][nf], al[mf], bh[nf]);
                }
        }
        __syncthreads();
    }

    int g = lane >> 2, qd = lane & 3;
#pragma unroll
    for (int mf = 0; mf < 4; mf++) {
#pragma unroll
        for (int half = 0; half < 2; half++) {
            int grow = by * BMH + wm + mf * 16 + g + half * 8;
#pragma unroll
            for (int nf = 0; nf < 4; nf++) {
                int gcol = bx * BNH + wn + nf * 8 + qd * 2;
                float v0 = acc[mf][nf][half*2 + 0];
                float v1 = acc[mf][nf][half*2 + 1];
                size_t o = (size_t)grow * Ndim + gcol;
                if (mode == 0) {
                    C[o] = v0; C[o+1] = v1;
                } else if (mode == 1) {
                    C[o] = v0 + resid[o]; C[o+1] = v1 + resid[o+1];
                } else if (mode == 2) {
                    float g0 = gelu_f(v0 + bias[gcol]);
                    float g1 = gelu_f(v1 + bias[gcol+1]);
                    __nv_bfloat16 hh, ll;
                    split_bf16(g0, hh, ll); Oh[o] = hh; Ol[o] = ll;
                    split_bf16(g1, hh, ll); Oh[o+1] = hh; Ol[o+1] = ll;
                } else if (mode == 3) {
                    C[o]   = v0 + bias[gcol]   + resid[o];
                    C[o+1] = v1 + bias[gcol+1] + resid[o+1];
                } else {
                    __nv_bfloat16 hh, ll;
                    split_bf16(v0, hh, ll); Oh[o] = hh; Ol[o] = ll;
                    split_bf16(v1, hh, ll); Oh[o+1] = hh; Ol[o+1] = ll;
                }
            }
        }
    }
}

// ---------------- HMMA flash attention (bf16x3, online softmax) --------------
// Block: 128 q-rows of one (b,h), 8 warps x m16. K tiles of 64, double-buffered.
__global__ __launch_bounds__(256, 1)
void flash_attn_hmma(const __nv_bfloat16* __restrict__ qh, const __nv_bfloat16* __restrict__ ql,
                     const __nv_bfloat16* __restrict__ kh, const __nv_bfloat16* __restrict__ kl,
                     const __nv_bfloat16* __restrict__ vh, const __nv_bfloat16* __restrict__ vl,
                     __nv_bfloat16* __restrict__ ctx_hi, __nv_bfloat16* __restrict__ ctx_lo)
{
    extern __shared__ char fs[];
    uint32_t sb = smem_to_u32(fs);
    int tid = threadIdx.x, wid = tid >> 5, lane = tid & 31;
    int g = lane >> 2, qd = lane & 3;
    int qt = blockIdx.x, bh = blockIdx.y;
    int b = bh >> 4, h = bh & 15;
    int q0 = qt * AQT;

    const __nv_bfloat16* qhb = qh + ((size_t)(b*SS + q0)) * DD + h * DHH;
    const __nv_bfloat16* qlb = ql + ((size_t)(b*SS + q0)) * DD + h * DHH;
    const __nv_bfloat16* khb = kh + ((size_t)(b*SS)) * DD + h * DHH;
    const __nv_bfloat16* klb = kl + ((size_t)(b*SS)) * DD + h * DHH;
    const __nv_bfloat16* vhb = vh + ((size_t)(b*SS)) * DD + h * DHH;
    const __nv_bfloat16* vlb = vl + ((size_t)(b*SS)) * DD + h * DHH;

    // K/V tile: 4 matrices x 64 rows x 64 bf16 (128B = 8 segs of 16B per row)
    auto load_tile = [&](int t, int s) {
        uint32_t st = sb + AST0 + s * ASTAGE;
        const __nv_bfloat16* srcs[4] = {khb, klb, vhb, vlb};
#pragma unroll
        for (int i = tid; i < 2048; i += 256) {
            int mtx = i >> 9;
            int j = i & 511;
            int row = j >> 3, seg = j & 7;
            uint32_t so = st + mtx * 9216 + row * ASTR + seg * 16;
            cp16(so, srcs[mtx] + (size_t)(t*AKT + row) * DD + seg * 8);
        }
    };

    // Q tile: 2 matrices x 128 rows x 64 bf16 (8 segs of 16B per row)
#pragma unroll
    for (int i = tid; i < 2048; i += 256) {
        int mtx = i >> 10;
        int j = i & 1023;
        int row = j >> 3, seg = j & 7;
        uint32_t so = sb + (mtx ? AQL_OFF : AQH_OFF) + row * ASTR + seg * 16;
        const __nv_bfloat16* src = (mtx ? qlb : qhb) + (size_t)row * DD + seg * 8;
        cp16(so, src);
    }
    load_tile(0, 0);
    cp_commit();
    load_tile(1, 1);
    cp_commit();

    float oacc[8][4];
#pragma unroll
    for (int i = 0; i < 8; i++)
#pragma unroll
        for (int j = 0; j < 4; j++) oacc[i][j] = 0.f;
    float m0 = -INFINITY, m1 = -INFINITY, l0 = 0.f, l1 = 0.f;
    uint32_t qfh[4][4], qfl[4][4];

    int ntiles = SS / AKT;   // 32
    for (int t = 0; t < ntiles; t++) {
        int s = t & 1;
        cp_wait1();
        __syncthreads();

        if (t == 0) {
#pragma unroll
            for (int ks = 0; ks < 4; ks++) {
                int r = wid * 16 + (lane & 15);
                uint32_t col = ks * 16 + (lane >> 4) * 8;
                uint32_t ad = sb + AQH_OFF + r * ASTR + col * 2;
                ldmx4(qfh[ks], ad);
                ldmx4(qfl[ks], ad + (AQL_OFF - AQH_OFF));
            }
        }

        uint32_t stb = sb + AST0 + s * ASTAGE;

        // ---- S = Q K^T ----
        float sacc[8][4];
#pragma unroll
        for (int i = 0; i < 8; i++)
#pragma unroll
            for (int j = 0; j < 4; j++) sacc[i][j] = 0.f;
#pragma unroll
        for (int ks = 0; ks < 4; ks++) {
#pragma unroll
            for (int nf2 = 0; nf2 < 4; nf2++) {
                int r = nf2 * 16 + ((lane >> 3) & 1) * 8 + (lane & 7);
                uint32_t colb = ks * 16 + (lane >> 4) * 8;
                uint32_t ad = stb + r * ASTR + colb * 2;
                uint32_t tb[4], kh0[2], kh1[2], kl0[2], kl1[2];
                ldmx4(tb, ad);
                kh0[0] = tb[0]; kh0[1] = tb[2]; kh1[0] = tb[1]; kh1[1] = tb[3];
                ldmx4(tb, ad + 9216);
                kl0[0] = tb[0]; kl0[1] = tb[2]; kl1[0] = tb[1]; kl1[1] = tb[3];
                mma_bf16(sacc[nf2*2],   qfh[ks], kh0);
                mma_bf16(sacc[nf2*2],   qfh[ks], kl0);
                mma_bf16(sacc[nf2*2],   qfl[ks], kh0);
                mma_bf16(sacc[nf2*2+1], qfh[ks], kh1);
                mma_bf16(sacc[nf2*2+1], qfh[ks], kl1);
                mma_bf16(sacc[nf2*2+1], qfl[ks], kh1);
            }
        }

        // ---- online softmax on fragments ----
        float mx0 = -INFINITY, mx1 = -INFINITY;
#pragma unroll
        for (int nf = 0; nf < 8; nf++) {
            mx0 = fmaxf(mx0, fmaxf(sacc[nf][0], sacc[nf][1]));
            mx1 = fmaxf(mx1, fmaxf(sacc[nf][2], sacc[nf][3]));
        }
        mx0 = fmaxf(mx0, __shfl_xor_sync(0xffffffffu, mx0, 1));
        mx0 = fmaxf(mx0, __shfl_xor_sync(0xffffffffu, mx0, 2));
        mx1 = fmaxf(mx1, __shfl_xor_sync(0xffffffffu, mx1, 1));
        mx1 = fmaxf(mx1, __shfl_xor_sync(0xffffffffu, mx1, 2));
        float mnew0 = fmaxf(m0, mx0), mnew1 = fmaxf(m1, mx1);
        float corr0 = __expf(m0 - mnew0), corr1 = __expf(m1 - mnew1);

        uint32_t ph[4][4], pl[4][4];
        float ps0 = 0.f, ps1 = 0.f;
#pragma unroll
        for (int nf = 0; nf < 8; nf++) {
            float p0 = __expf(sacc[nf][0] - mnew0);
            float p1 = __expf(sacc[nf][1] - mnew0);
            float p2 = __expf(sacc[nf][2] - mnew1);
            float p3 = __expf(sacc[nf][3] - mnew1);
            ps0 += p0 + p1; ps1 += p2 + p3;
            __nv_bfloat162 h01 = __floats2bfloat162_rn(p0, p1);
            __nv_bfloat162 h23 = __floats2bfloat162_rn(p2, p3);
            float e0 = p0 - __low2float(h01), e1 = p1 - __high2float(h01);
            float e2 = p2 - __low2float(h23), e3 = p3 - __high2float(h23);
            int kks = nf >> 1, hf = nf & 1;
            ph[kks][hf*2 + 0] = *reinterpret_cast<uint32_t*>(&h01);
            ph[kks][hf*2 + 1] = *reinterpret_cast<uint32_t*>(&h23);
            pl[kks][hf*2 + 0] = pack_bf2(e0, e1);
            pl[kks][hf*2 + 1] = pack_bf2(e2, e3);
        }
        ps0 += __shfl_xor_sync(0xffffffffu, ps0, 1);
        ps0 += __shfl_xor_sync(0xffffffffu, ps0, 2);
        ps1 += __shfl_xor_sync(0xffffffffu, ps1, 1);
        ps1 += __shfl_xor_sync(0xffffffffu, ps1, 2);
        l0 = l0 * corr0 + ps0;
        l1 = l1 * corr1 + ps1;
        m0 = mnew0; m1 = mnew1;
#pragma unroll
        for (int nf = 0; nf < 8; nf++) {
            oacc[nf][0] *= corr0; oacc[nf][1] *= corr0;
            oacc[nf][2] *= corr1; oacc[nf][3] *= corr1;
        }

        // ---- O += P V ----
#pragma unroll
        for (int kks = 0; kks < 4; kks++) {
#pragma unroll
            for (int nf2 = 0; nf2 < 4; nf2++) {
                int r = kks * 16 + (lane & 15);
                uint32_t colb = nf2 * 16 + (lane >> 4) * 8;
                uint32_t vd = stb + 18432 + r * ASTR + colb * 2;
                uint32_t tb[4], vh0[2], vh1[2], vl0[2], vl1[2];
                ldmx4t(tb, vd);
                vh0[0] = tb[0]; vh0[1] = tb[1]; vh1[0] = tb[2]; vh1[1] = tb[3];
                ldmx4t(tb, vd + 9216);
                vl0[0] = tb[0]; vl0[1] = tb[1]; vl1[0] = tb[2]; vl1[1] = tb[3];
                mma_bf16(oacc[nf2*2],   ph[kks], vh0);
                mma_bf16(oacc[nf2*2],   ph[kks], vl0);
                mma_bf16(oacc[nf2*2],   pl[kks], vh0);
                mma_bf16(oacc[nf2*2+1], ph[kks], vh1);
                mma_bf16(oacc[nf2*2+1], ph[kks], vl1);
                mma_bf16(oacc[nf2*2+1], pl[kks], vh1);
            }
        }
        __syncthreads();
        if (t + 2 < ntiles) load_tile(t + 2, s);
        cp_commit();   // unconditional: empty tail groups force final tile to retire
    }

    // ---- epilogue ----
    float inv0 = 1.f / l0, inv1 = 1.f / l1;
    size_t row0 = (size_t)(b*SS + q0 + wid*16 + g);
    size_t row1 = row0 + 8;
#pragma unroll
    for (int nf = 0; nf < 8; nf++) {
        int col = h * DHH + nf * 8 + 2 * qd;
        float v00 = oacc[nf][0] * inv0, v01 = oacc[nf][1] * inv0;
        float v10 = oacc[nf][2] * inv1, v11 = oacc[nf][3] * inv1;
        __nv_bfloat162 hi01 = __floats2bfloat162_rn(v00, v01);
        __nv_bfloat162 lo01 = __floats2bfloat162_rn(v00 - __low2float(hi01), v01 - __high2float(hi01));
        __nv_bfloat162 hi23 = __floats2bfloat162_rn(v10, v11);
        __nv_bfloat162 lo23 = __floats2bfloat162_rn(v10 - __low2float(hi23), v11 - __high2float(hi23));
        *reinterpret_cast<__nv_bfloat162*>(ctx_hi + row0*DD + col) = hi01;
        *reinterpret_cast<__nv_bfloat162*>(ctx_lo + row0*DD + col) = lo01;
        *reinterpret_cast<__nv_bfloat162*>(ctx_hi + row1*DD + col) = hi23;
        *reinterpret_cast<__nv_bfloat162*>(ctx_lo + row1*DD + col) = lo23;
    }
}

// ---------------- launch ----------------------------------------------------
extern "C" void kernel_launch(void* const* d_in, const int* in_sizes, int n_in,
                              void* d_out, int out_size)
{
    (void)in_sizes; (void)n_in; (void)out_size;
    const float* x     = (const float*)d_in[0];
    const float* ln1_s = (const float*)d_in[1];
    const float* ln1_b = (const float*)d_in[2];
    const float* wk    = (const float*)d_in[3];
    const float* wq    = (const float*)d_in[4];
    const float* wv    = (const float*)d_in[5];
    const float* wo    = (const float*)d_in[6];
    const float* ln2_s = (const float*)d_in[7];
    const float* ln2_b = (const float*)d_in[8];
    const float* w1    = (const float*)d_in[9];
    const float* b1    = (const float*)d_in[10];
    const float* w2    = (const float*)d_in[11];
    const float* b2    = (const float*)d_in[12];
    float* out = (float*)d_out;

    static int configured = 0;
    if (!configured) {
        cudaFuncSetAttribute(gemm_hmma, cudaFuncAttributeMaxDynamicSharedMemorySize, HSMEM);
        cudaFuncSetAttribute(flash_attn_hmma, cudaFuncAttributeMaxDynamicSharedMemorySize, ASMEM);
        configured = 1;
    }

    __nv_bfloat16 *h_hi, *h_lo, *ctx_hi, *ctx_lo, *h2_hi, *h2_lo, *mid_hi, *mid_lo;
    __nv_bfloat16 *qhp, *qlp, *khp, *klp, *vhp, *vlp;
    __nv_bfloat16 *wqt_h, *wqt_l, *wkt_h, *wkt_l, *wvt_h, *wvt_l, *wot_h, *wot_l;
    __nv_bfloat16 *w1t_h, *w1t_l, *w2t_h, *w2t_l;
    float *q, *k, *mlpin;
    cudaGetSymbolAddress((void**)&h_hi,  g_h_hi);   cudaGetSymbolAddress((void**)&h_lo,  g_h_lo);
    cudaGetSymbolAddress((void**)&q,     g_q);      cudaGetSymbolAddress((void**)&k,     g_k);
    cudaGetSymbolAddress((void**)&qhp,   g_qh);     cudaGetSymbolAddress((void**)&qlp,   g_ql);
    cudaGetSymbolAddress((void**)&khp,   g_kh);     cudaGetSymbolAddress((void**)&klp,   g_kl);
    cudaGetSymbolAddress((void**)&vhp,   g_vh);     cudaGetSymbolAddress((void**)&vlp,   g_vl);
    cudaGetSymbolAddress((void**)&ctx_hi,g_ctx_hi); cudaGetSymbolAddress((void**)&ctx_lo,g_ctx_lo);
    cudaGetSymbolAddress((void**)&mlpin, g_mlpin);
    cudaGetSymbolAddress((void**)&h2_hi, g_h2_hi);  cudaGetSymbolAddress((void**)&h2_lo, g_h2_lo);
    cudaGetSymbolAddress((void**)&mid_hi,g_mid_hi); cudaGetSymbolAddress((void**)&mid_lo,g_mid_lo);
    cudaGetSymbolAddress((void**)&wqt_h, g_wqt_h);  cudaGetSymbolAddress((void**)&wqt_l, g_wqt_l);
    cudaGetSymbolAddress((void**)&wkt_h, g_wkt_h);  cudaGetSymbolAddress((void**)&wkt_l, g_wkt_l);
    cudaGetSymbolAddress((void**)&wvt_h, g_wvt_h);  cudaGetSymbolAddress((void**)&wvt_l, g_wvt_l);
    cudaGetSymbolAddress((void**)&wot_h, g_wot_h);  cudaGetSymbolAddress((void**)&wot_l, g_wot_l);
    cudaGetSymbolAddress((void**)&w1t_h, g_w1t_h);  cudaGetSymbolAddress((void**)&w1t_l, g_w1t_l);
    cudaGetSymbolAddress((void**)&w2t_h, g_w2t_h);  cudaGetSymbolAddress((void**)&w2t_l, g_w2t_l);

    dim3 tb(32, 8);
    tconv<<<dim3(DD/32, DD/32), tb>>>(wq, wqt_h, wqt_l, DD, DD);
    tconv<<<dim3(DD/32, DD/32), tb>>>(wk, wkt_h, wkt_l, DD, DD);
    tconv<<<dim3(DD/32, DD/32), tb>>>(wv, wvt_h, wvt_l, DD, DD);
    tconv<<<dim3(DD/32, DD/32), tb>>>(wo, wot_h, wot_l, DD, DD);
    tconv<<<dim3(MM/32, DD/32), tb>>>(w1, w1t_h, w1t_l, DD, MM);
    tconv<<<dim3(DD/32, MM/32), tb>>>(w2, w2t_h, w2t_l, MM, DD);

    // 1. LN1 -> bf16 hi/lo
    ln_bf16<<<ROWS, 256>>>(x, ln1_s, ln1_b, h_hi, h_lo);

    // 2. QKV projections (q,k fp32 for RoPE; v straight to bf16 hi/lo)
    dim3 gDD(DD/BNH, ROWS/BMH);
    gemm_hmma<<<gDD, 256, HSMEM>>>(h_hi, h_lo, wqt_h, wqt_l, q, DD, DD,
                                   nullptr, nullptr, nullptr, nullptr, 0);
    gemm_hmma<<<gDD, 256, HSMEM>>>(h_hi, h_lo, wkt_h, wkt_l, k, DD, DD,
                                   nullptr, nullptr, nullptr, nullptr, 0);
    gemm_hmma<<<gDD, 256, HSMEM>>>(h_hi, h_lo, wvt_h, wvt_l, nullptr, DD, DD,
                                   nullptr, nullptr, vhp, vlp, 4);

    // 3. RoPE + split (q scaled by 1/8)
    rope_split<<<(BB*SS*HH*32)/256, 256>>>(q, k, qhp, qlp, khp, klp);

    // 4. HMMA flash attention -> ctx bf16 hi/lo
    flash_attn_hmma<<<dim3(SS/AQT, BB*HH), 256, ASMEM>>>(qhp, qlp, khp, klp, vhp, vlp,
                                                         ctx_hi, ctx_lo);

    // 5. WO projection + residual x -> mlpin (fp32)
    gemm_hmma<<<gDD, 256, HSMEM>>>(ctx_hi, ctx_lo, wot_h, wot_l, mlpin, DD, DD,
                                   nullptr, x, nullptr, nullptr, 1);

    // 6. LN2 -> bf16 hi/lo
    ln_bf16<<<ROWS, 256>>>(mlpin, ln2_s, ln2_b, h2_hi, h2_lo);

    // 7. MLP up: gelu(h2@w1+b1) -> mid bf16 hi/lo
    gemm_hmma<<<dim3(MM/BNH, ROWS/BMH), 256, HSMEM>>>(h2_hi, h2_lo, w1t_h, w1t_l,
                                   nullptr, MM, DD, b1, nullptr, mid_hi, mid_lo, 2);

    // 8. MLP down + bias + residual -> out (fp32)
    gemm_hmma<<<gDD, 256, HSMEM>>>(mid_hi, mid_lo, w2t_h, w2t_l, out, DD, MM,
                                   b2, mlpin, nullptr, nullptr, 3);
}